// round 6
// baseline (speedup 1.0000x reference)
#include <cuda_runtime.h>
#include <cuda_fp16.h>
#include <math.h>

#define NN   100000
#define NE   1600000
#define FIN  128
#define NH   8
#define FH   16
#define HF   128     // NH*FH
#define NC   40
#define NBLK 98      // ceil(NN/1024)

typedef unsigned long long u64;

// ----------------------------------------------------------------------------
// Packed f32x2 helpers (Blackwell FFMA2: 2 fp32 FMA per issue slot)
// ----------------------------------------------------------------------------
__device__ __forceinline__ u64 pack2(float x, float y) {
    u64 p;
    asm("mov.b64 %0, {%1, %2};" : "=l"(p) : "f"(x), "f"(y));
    return p;
}
__device__ __forceinline__ float2 unpack2(u64 p) {
    float2 r;
    asm("mov.b64 {%0, %1}, %2;" : "=f"(r.x), "=f"(r.y) : "l"(p));
    return r;
}
__device__ __forceinline__ void fma2(u64& acc, u64 a, u64 b) {
    asm("fma.rn.f32x2 %0, %1, %2, %0;" : "+l"(acc) : "l"(a), "l"(b));
}

// ----------------------------------------------------------------------------
// Scratch (device globals; rewritten or zeroed every launch)
// Feature buffers stored fp16 (gather format only; all math fp32)
// ----------------------------------------------------------------------------
__device__ __half g_h1h[NN * HF];   // layer1 transformed features (fp16 mirror)
__device__ float g_as1[NN * NH];
__device__ float g_ad1[NN * NH];
__device__ float g_act[NN * HF];    // layer1 output after ELU (fp32: feeds GEMM2)
__device__ __half g_h2h[NN * NC];   // layer2 transformed features (fp16 mirror)
__device__ float g_as2[NN];
__device__ float g_ad2[NN];
__device__ int   g_deg[NN];
__device__ int   g_cur[NN];
__device__ int   g_off[NN + 1];
__device__ int   g_bsum[128];
__device__ int   g_srcs[NE];        // src ids grouped by dst (CSR), per-segment sorted by src
__device__ int   g_is64;

// ----------------------------------------------------------------------------
// Zero counters + edge dtype detection (jax may emit int32 or int64)
// ----------------------------------------------------------------------------
__global__ void k_zero(const void* src) {
    int i = blockIdx.x * blockDim.x + threadIdx.x;
    if (i < NN) { g_deg[i] = 0; g_cur[i] = 0; }
    if (i == 0) {
        const long long* p = (const long long*)src;
        int ok = 1;
        #pragma unroll
        for (int q = 0; q < 16; q++) {
            long long v = p[q];
            if (v < 0 || v >= NN) ok = 0;
        }
        g_is64 = ok;
    }
}

__device__ __forceinline__ int edge_get(const void* p, int i, int is64) {
    return is64 ? (int)((const long long*)p)[i] : ((const int*)p)[i];
}

// ----------------------------------------------------------------------------
// GEMM1 + fused alpha1: h1 (fp16 out) = x @ W1; as1/ad1 = per-head dots
// 128x128 tile, 256 threads, 8x8 register tile (row-paired f32x2), BK=16,
// double-buffered smem with register prefetch.
// ----------------------------------------------------------------------------
__global__ void k_gemm1(const float* __restrict__ x, const float* __restrict__ W,
                        const float* __restrict__ avs, const float* __restrict__ avd) {
    __shared__ float As[2][16][128];
    __shared__ float Bs[2][16][128];
    int tid = threadIdx.x;
    int tx = tid & 15, ty = tid >> 4;          // 16x16
    int rowBase = blockIdx.x * 128;

    int qa0 = tid,        qa1 = tid + 256;
    int ra0 = qa0 >> 2,   ca0 = (qa0 & 3) * 4;
    int ra1 = qa1 >> 2,   ca1 = (qa1 & 3) * 4;
    int ga0 = rowBase + ra0, ga1 = rowBase + ra1;
    int kb0 = qa0 >> 5,   cb0 = (qa0 & 31) * 4;
    int kb1 = qa1 >> 5,   cb1 = (qa1 & 31) * 4;

    u64 acc2[4][8];
    #pragma unroll
    for (int i = 0; i < 4; i++)
        #pragma unroll
        for (int j = 0; j < 8; j++) acc2[i][j] = 0ULL;

    float4 rA0, rA1, rB0, rB1;

    {
        rA0 = (ga0 < NN) ? *(const float4*)&x[(size_t)ga0 * FIN + 0 + ca0] : make_float4(0,0,0,0);
        rA1 = (ga1 < NN) ? *(const float4*)&x[(size_t)ga1 * FIN + 0 + ca1] : make_float4(0,0,0,0);
        rB0 = *(const float4*)&W[(size_t)(0 + kb0) * HF + cb0];
        rB1 = *(const float4*)&W[(size_t)(0 + kb1) * HF + cb1];
        As[0][ca0 + 0][ra0] = rA0.x; As[0][ca0 + 1][ra0] = rA0.y;
        As[0][ca0 + 2][ra0] = rA0.z; As[0][ca0 + 3][ra0] = rA0.w;
        As[0][ca1 + 0][ra1] = rA1.x; As[0][ca1 + 1][ra1] = rA1.y;
        As[0][ca1 + 2][ra1] = rA1.z; As[0][ca1 + 3][ra1] = rA1.w;
        *((float4*)&Bs[0][kb0][cb0]) = rB0;
        *((float4*)&Bs[0][kb1][cb1]) = rB1;
    }
    __syncthreads();

    #pragma unroll
    for (int t = 0; t < 8; t++) {
        int cur = t & 1;
        if (t < 7) {
            int kt = 16 * (t + 1);
            rA0 = (ga0 < NN) ? *(const float4*)&x[(size_t)ga0 * FIN + kt + ca0] : make_float4(0,0,0,0);
            rA1 = (ga1 < NN) ? *(const float4*)&x[(size_t)ga1 * FIN + kt + ca1] : make_float4(0,0,0,0);
            rB0 = *(const float4*)&W[(size_t)(kt + kb0) * HF + cb0];
            rB1 = *(const float4*)&W[(size_t)(kt + kb1) * HF + cb1];
        }

        #pragma unroll
        for (int k = 0; k < 16; k++) {
            u64 A0 = *(const u64*)&As[cur][k][ty * 8 + 0];
            u64 A1 = *(const u64*)&As[cur][k][ty * 8 + 2];
            u64 A2 = *(const u64*)&As[cur][k][ty * 8 + 4];
            u64 A3 = *(const u64*)&As[cur][k][ty * 8 + 6];
            float4 b0 = *(const float4*)&Bs[cur][k][tx * 8];
            float4 b1 = *(const float4*)&Bs[cur][k][tx * 8 + 4];
            u64 bb[8];
            bb[0] = pack2(b0.x, b0.x); bb[1] = pack2(b0.y, b0.y);
            bb[2] = pack2(b0.z, b0.z); bb[3] = pack2(b0.w, b0.w);
            bb[4] = pack2(b1.x, b1.x); bb[5] = pack2(b1.y, b1.y);
            bb[6] = pack2(b1.z, b1.z); bb[7] = pack2(b1.w, b1.w);
            #pragma unroll
            for (int j = 0; j < 8; j++) {
                fma2(acc2[0][j], A0, bb[j]);
                fma2(acc2[1][j], A1, bb[j]);
                fma2(acc2[2][j], A2, bb[j]);
                fma2(acc2[3][j], A3, bb[j]);
            }
        }

        if (t < 7) {
            int nxt = cur ^ 1;
            __syncthreads();
            As[nxt][ca0 + 0][ra0] = rA0.x; As[nxt][ca0 + 1][ra0] = rA0.y;
            As[nxt][ca0 + 2][ra0] = rA0.z; As[nxt][ca0 + 3][ra0] = rA0.w;
            As[nxt][ca1 + 0][ra1] = rA1.x; As[nxt][ca1 + 1][ra1] = rA1.y;
            As[nxt][ca1 + 2][ra1] = rA1.z; As[nxt][ca1 + 3][ra1] = rA1.w;
            *((float4*)&Bs[nxt][kb0][cb0]) = rB0;
            *((float4*)&Bs[nxt][kb1][cb1]) = rB1;
            __syncthreads();
        }
    }

    float acc[8][8];
    #pragma unroll
    for (int i2 = 0; i2 < 4; i2++)
        #pragma unroll
        for (int j = 0; j < 8; j++) {
            float2 v = unpack2(acc2[i2][j]);
            acc[2 * i2 + 0][j] = v.x;
            acc[2 * i2 + 1][j] = v.y;
        }

    // store h1 as fp16 (thread tx owns cols [tx*8, tx*8+8) -> 16B per row)
    #pragma unroll
    for (int i = 0; i < 8; i++) {
        int grow = rowBase + ty * 8 + i;
        if (grow < NN) {
            __half hb[8];
            #pragma unroll
            for (int j = 0; j < 8; j++) hb[j] = __float2half_rn(acc[i][j]);
            *(uint4*)&g_h1h[(size_t)grow * HF + tx * 8] = *(uint4*)hb;
        }
    }

    // fused alpha epilogue (fp32): thread tx owns cols [tx*8, tx*8+8) -> head tx/2
    float av_s[8], av_d[8];
    #pragma unroll
    for (int j = 0; j < 8; j++) { av_s[j] = avs[tx * 8 + j]; av_d[j] = avd[tx * 8 + j]; }
    #pragma unroll
    for (int i = 0; i < 8; i++) {
        float s = 0.f, d = 0.f;
        #pragma unroll
        for (int j = 0; j < 8; j++) { s += acc[i][j] * av_s[j]; d += acc[i][j] * av_d[j]; }
        s += __shfl_xor_sync(0xffffffffu, s, 1);
        d += __shfl_xor_sync(0xffffffffu, d, 1);
        if ((tx & 1) == 0) {
            int grow = rowBase + ty * 8 + i;
            if (grow < NN) {
                g_as1[grow * NH + (tx >> 1)] = s;
                g_ad1[grow * NH + (tx >> 1)] = d;
            }
        }
    }
}

// ----------------------------------------------------------------------------
// Degree histogram
// ----------------------------------------------------------------------------
__global__ void k_hist(const void* edst) {
    int is64 = g_is64;
    int stride = gridDim.x * blockDim.x;
    for (int e = blockIdx.x * blockDim.x + threadIdx.x; e < NE; e += stride) {
        atomicAdd(&g_deg[edge_get(edst, e, is64)], 1);
    }
}

// ----------------------------------------------------------------------------
// Two-level exclusive scan
// ----------------------------------------------------------------------------
__global__ void k_scan1() {
    __shared__ int sh[1024];
    int tid = threadIdx.x;
    int i = blockIdx.x * 1024 + tid;
    int v = (i < NN) ? g_deg[i] : 0;
    sh[tid] = v;
    __syncthreads();
    #pragma unroll
    for (int ofs = 1; ofs < 1024; ofs <<= 1) {
        int t = (tid >= ofs) ? sh[tid - ofs] : 0;
        __syncthreads();
        sh[tid] += t;
        __syncthreads();
    }
    if (i < NN) g_off[i] = sh[tid] - v;
    if (tid == 1023) g_bsum[blockIdx.x] = sh[1023];
}

__global__ void k_scan2() {
    __shared__ int sh[128];
    int tid = threadIdx.x;
    int v = (tid < NBLK) ? g_bsum[tid] : 0;
    sh[tid] = v;
    __syncthreads();
    #pragma unroll
    for (int ofs = 1; ofs < 128; ofs <<= 1) {
        int t = (tid >= ofs) ? sh[tid - ofs] : 0;
        __syncthreads();
        sh[tid] += t;
        __syncthreads();
    }
    if (tid < NBLK) g_bsum[tid] = sh[tid] - v;   // exclusive
}

__global__ void k_scan3() {
    int i = blockIdx.x * 1024 + threadIdx.x;
    if (i < NN) g_off[i] += g_bsum[blockIdx.x];
    if (i == 0) g_off[NN] = NE;
}

// ----------------------------------------------------------------------------
// Scatter edges into CSR slots
// ----------------------------------------------------------------------------
__global__ void k_scatter(const void* esrc, const void* edst) {
    int is64 = g_is64;
    int stride = gridDim.x * blockDim.x;
    for (int e = blockIdx.x * blockDim.x + threadIdx.x; e < NE; e += stride) {
        int d = edge_get(edst, e, is64);
        int s = edge_get(esrc, e, is64);
        int pos = g_off[d] + atomicAdd(&g_cur[d], 1);
        g_srcs[pos] = s;
    }
}

// ----------------------------------------------------------------------------
// Per-segment sort by src (canonical order => determinism).
// ----------------------------------------------------------------------------
#define SORT_T 128
#define SORT_D 64
__global__ void __launch_bounds__(SORT_T) k_sort() {
    __shared__ int sbuf[SORT_D * SORT_T];
    int t = threadIdx.x;
    int n = blockIdx.x * SORT_T + t;
    if (n >= NN) return;
    int b = g_off[n], e = g_off[n + 1];
    int deg = e - b;
    if (deg <= 1) return;
    if (deg <= SORT_D) {
        for (int i = 0; i < deg; i++) sbuf[i * SORT_T + t] = g_srcs[b + i];
        for (int i = 1; i < deg; i++) {
            int v = sbuf[i * SORT_T + t], j = i - 1;
            while (j >= 0 && sbuf[j * SORT_T + t] > v) {
                sbuf[(j + 1) * SORT_T + t] = sbuf[j * SORT_T + t];
                j--;
            }
            sbuf[(j + 1) * SORT_T + t] = v;
        }
        for (int i = 0; i < deg; i++) g_srcs[b + i] = sbuf[i * SORT_T + t];
    } else {
        for (int i = 1; i < deg; i++) {
            int v = g_srcs[b + i], j = i - 1;
            while (j >= 0 && g_srcs[b + j] > v) { g_srcs[b + j + 1] = g_srcs[b + j]; j--; }
            g_srcs[b + j + 1] = v;
        }
    }
}

// ----------------------------------------------------------------------------
// Layer-1 softmax + aggregate + bias + ELU. Warp per dst node.
// Lane l owns features [l*4, l*4+4) (fp16 gather, fp32 math), head = l/4.
// ----------------------------------------------------------------------------
__global__ void k_agg1(const float* __restrict__ b1) {
    int warp = (blockIdx.x * blockDim.x + threadIdx.x) >> 5;
    int lane = threadIdx.x & 31;
    if (warp >= NN) return;
    int d = warp;
    int beg = g_off[d], end = g_off[d + 1];
    int hd = lane >> 2;
    int f0 = lane * 4;
    float ad = g_ad1[d * NH + hd];

    float sum = 0.f;
    float4 acc = make_float4(0.f, 0.f, 0.f, 0.f);
    if (beg < end) {
        int s = g_srcs[beg];
        float a = g_as1[s * NH + hd];
        uint2 hraw = *(const uint2*)&g_h1h[(size_t)s * HF + f0];
        for (int i = beg + 1; i < end; i++) {
            int s2 = g_srcs[i];
            float a2 = g_as1[s2 * NH + hd];
            uint2 hraw2 = *(const uint2*)&g_h1h[(size_t)s2 * HF + f0];
            float e = a + ad;
            e = fmaxf(e, 0.2f * e);
            float p = __expf(e);
            sum += p;
            float2 f01 = __half22float2(*(__half2*)&hraw.x);
            float2 f23 = __half22float2(*(__half2*)&hraw.y);
            acc.x += p * f01.x; acc.y += p * f01.y; acc.z += p * f23.x; acc.w += p * f23.y;
            a = a2; hraw = hraw2;
        }
        float e = a + ad;
        e = fmaxf(e, 0.2f * e);
        float p = __expf(e);
        sum += p;
        float2 f01 = __half22float2(*(__half2*)&hraw.x);
        float2 f23 = __half22float2(*(__half2*)&hraw.y);
        acc.x += p * f01.x; acc.y += p * f01.y; acc.z += p * f23.x; acc.w += p * f23.y;
    }

    float inv = (end > beg) ? 1.f / sum : 0.f;
    float4 b = *(const float4*)&b1[f0];
    float4 r;
    r.x = acc.x * inv + b.x;
    r.y = acc.y * inv + b.y;
    r.z = acc.z * inv + b.z;
    r.w = acc.w * inv + b.w;
    r.x = r.x > 0.f ? r.x : expm1f(r.x);
    r.y = r.y > 0.f ? r.y : expm1f(r.y);
    r.z = r.z > 0.f ? r.z : expm1f(r.z);
    r.w = r.w > 0.f ? r.w : expm1f(r.w);
    *(float4*)&g_act[(size_t)d * HF + f0] = r;
}

// ----------------------------------------------------------------------------
// GEMM2 + fused alpha2: h2 (fp16 out) = g_act @ W2 (128x40, 4x5/thread, f32x2)
// ----------------------------------------------------------------------------
__global__ void k_gemm2(const float* __restrict__ W,
                        const float* __restrict__ avs, const float* __restrict__ avd) {
    __shared__ float As[16][128];
    __shared__ float Bs[16][NC];
    int tid = threadIdx.x;
    int tx = tid & 7, ty = tid >> 3;
    int rowBase = blockIdx.x * 128;

    u64 acc2[2][5];
    #pragma unroll
    for (int i = 0; i < 2; i++)
        #pragma unroll
        for (int j = 0; j < 5; j++) acc2[i][j] = 0ULL;

    for (int kt = 0; kt < HF; kt += 16) {
        #pragma unroll
        for (int l = 0; l < 2; l++) {
            int q  = tid + l * 256;
            int r  = q >> 2;
            int c4 = q & 3;
            int grow = rowBase + r;
            float4 v = make_float4(0.f, 0.f, 0.f, 0.f);
            if (grow < NN) v = *(const float4*)&g_act[(size_t)grow * HF + kt + c4 * 4];
            As[c4 * 4 + 0][r] = v.x;
            As[c4 * 4 + 1][r] = v.y;
            As[c4 * 4 + 2][r] = v.z;
            As[c4 * 4 + 3][r] = v.w;
        }
        #pragma unroll
        for (int l = 0; l < 3; l++) {
            int idx = tid + l * 256;
            if (idx < 16 * NC) {
                int kr = idx / NC, c = idx % NC;
                Bs[kr][c] = W[(size_t)(kt + kr) * NC + c];
            }
        }
        __syncthreads();

        #pragma unroll
        for (int k = 0; k < 16; k++) {
            u64 A0 = *(const u64*)&As[k][ty * 4 + 0];
            u64 A1 = *(const u64*)&As[k][ty * 4 + 2];
            u64 bb[5];
            #pragma unroll
            for (int j = 0; j < 5; j++) {
                float b = Bs[k][tx * 5 + j];
                bb[j] = pack2(b, b);
            }
            #pragma unroll
            for (int j = 0; j < 5; j++) {
                fma2(acc2[0][j], A0, bb[j]);
                fma2(acc2[1][j], A1, bb[j]);
            }
        }
        __syncthreads();
    }

    float acc[4][5];
    #pragma unroll
    for (int i2 = 0; i2 < 2; i2++)
        #pragma unroll
        for (int j = 0; j < 5; j++) {
            float2 v = unpack2(acc2[i2][j]);
            acc[2 * i2 + 0][j] = v.x;
            acc[2 * i2 + 1][j] = v.y;
        }

    float av_s[5], av_d[5];
    #pragma unroll
    for (int j = 0; j < 5; j++) { av_s[j] = avs[tx * 5 + j]; av_d[j] = avd[tx * 5 + j]; }

    #pragma unroll
    for (int i = 0; i < 4; i++) {
        int grow = rowBase + ty * 4 + i;
        float s = 0.f, d = 0.f;
        #pragma unroll
        for (int j = 0; j < 5; j++) { s += acc[i][j] * av_s[j]; d += acc[i][j] * av_d[j]; }
        #pragma unroll
        for (int o = 1; o < 8; o <<= 1) {
            s += __shfl_xor_sync(0xffffffffu, s, o);
            d += __shfl_xor_sync(0xffffffffu, d, o);
        }
        if (grow < NN) {
            #pragma unroll
            for (int j = 0; j < 5; j++)
                g_h2h[(size_t)grow * NC + tx * 5 + j] = __float2half_rn(acc[i][j]);
            if (tx == 0) { g_as2[grow] = s; g_ad2[grow] = d; }
        }
    }
}

// ----------------------------------------------------------------------------
// Layer-2 softmax + aggregate + bias. Warp per dst node, fp16 gather.
// Lanes 0..19 own 2 output cols each.
// ----------------------------------------------------------------------------
__global__ void k_agg2(const float* __restrict__ b2, float* __restrict__ out) {
    int warp = (blockIdx.x * blockDim.x + threadIdx.x) >> 5;
    int lane = threadIdx.x & 31;
    if (warp >= NN) return;
    int d = warp;
    int beg = g_off[d], end = g_off[d + 1];
    float ad = g_ad2[d];

    float sum = 0.f;
    float2 acc = make_float2(0.f, 0.f);
    int c0 = lane * 2;
    bool act = (lane < 20);
    if (beg < end) {
        int s = g_srcs[beg];
        float a = g_as2[s];
        unsigned hraw = act ? *(const unsigned*)&g_h2h[(size_t)s * NC + c0] : 0u;
        for (int i = beg + 1; i < end; i++) {
            int s2 = g_srcs[i];
            float a2 = g_as2[s2];
            unsigned hraw2 = act ? *(const unsigned*)&g_h2h[(size_t)s2 * NC + c0] : 0u;
            float e = a + ad;
            e = fmaxf(e, 0.2f * e);
            float p = __expf(e);
            sum += p;
            float2 hv = __half22float2(*(__half2*)&hraw);
            acc.x += p * hv.x; acc.y += p * hv.y;
            a = a2; hraw = hraw2;
        }
        float e = a + ad;
        e = fmaxf(e, 0.2f * e);
        float p = __expf(e);
        sum += p;
        float2 hv = __half22float2(*(__half2*)&hraw);
        acc.x += p * hv.x; acc.y += p * hv.y;
    }
    float inv = (end > beg) ? 1.f / sum : 0.f;
    if (act) {
        out[(size_t)d * NC + c0 + 0] = acc.x * inv + b2[c0 + 0];
        out[(size_t)d * NC + c0 + 1] = acc.y * inv + b2[c0 + 1];
    }
}

// ----------------------------------------------------------------------------
// Launch: fork prep chain (s2) parallel with GEMM1 (default), join before agg1
// ----------------------------------------------------------------------------
extern "C" void kernel_launch(void* const* d_in, const int* in_sizes, int n_in,
                              void* d_out, int out_size) {
    static cudaStream_t s2 = 0;
    static cudaEvent_t evFork = 0, evJoin = 0;
    if (!s2) {
        cudaStreamCreateWithFlags(&s2, cudaStreamNonBlocking);
        cudaEventCreateWithFlags(&evFork, cudaEventDisableTiming);
        cudaEventCreateWithFlags(&evJoin, cudaEventDisableTiming);
    }

    const float* x    = (const float*)d_in[0];
    const void*  esrc = d_in[1];
    const void*  edst = d_in[2];
    const float* W1   = (const float*)d_in[3];
    const float* as1  = (const float*)d_in[4];
    const float* ad1  = (const float*)d_in[5];
    const float* b1   = (const float*)d_in[6];
    const float* W2   = (const float*)d_in[7];
    const float* as2  = (const float*)d_in[8];
    const float* ad2  = (const float*)d_in[9];
    const float* b2   = (const float*)d_in[10];
    float* out = (float*)d_out;

    // fork: prep chain on s2
    cudaEventRecord(evFork, 0);
    cudaStreamWaitEvent(s2, evFork, 0);

    k_zero<<<(NN + 255) / 256, 256, 0, s2>>>(esrc);
    k_hist<<<2048, 256, 0, s2>>>(edst);
    k_scan1<<<NBLK, 1024, 0, s2>>>();
    k_scan2<<<1, 128, 0, s2>>>();
    k_scan3<<<NBLK, 1024, 0, s2>>>();
    k_scatter<<<2048, 256, 0, s2>>>(esrc, edst);
    k_sort<<<(NN + SORT_T - 1) / SORT_T, SORT_T, 0, s2>>>();
    cudaEventRecord(evJoin, s2);

    // concurrent: GEMM1 on default stream
    k_gemm1<<<(NN + 127) / 128, 256>>>(x, W1, as1, ad1);

    // join
    cudaStreamWaitEvent(0, evJoin, 0);

    k_agg1<<<(NN * 32 + 255) / 256, 256>>>(b1);
    k_gemm2<<<(NN + 127) / 128, 256>>>(W2, as2, ad2);
    k_agg2<<<(NN * 32 + 255) / 256, 256>>>(b2, out);
}

// round 7
// speedup vs baseline: 1.0055x; 1.0055x over previous
#include <cuda_runtime.h>
#include <cuda_fp16.h>
#include <math.h>

#define NN   100000
#define NE   1600000
#define FIN  128
#define NH   8
#define FH   16
#define HF   128     // NH*FH
#define NC   40
#define NBLK 98      // ceil(NN/1024)

typedef unsigned long long u64;

// ----------------------------------------------------------------------------
// Packed f32x2 helpers (Blackwell FFMA2: 2 fp32 FMA per issue slot)
// ----------------------------------------------------------------------------
__device__ __forceinline__ u64 pack2(float x, float y) {
    u64 p;
    asm("mov.b64 %0, {%1, %2};" : "=l"(p) : "f"(x), "f"(y));
    return p;
}
__device__ __forceinline__ float2 unpack2(u64 p) {
    float2 r;
    asm("mov.b64 {%0, %1}, %2;" : "=f"(r.x), "=f"(r.y) : "l"(p));
    return r;
}
__device__ __forceinline__ void fma2(u64& acc, u64 a, u64 b) {
    asm("fma.rn.f32x2 %0, %1, %2, %0;" : "+l"(acc) : "l"(a), "l"(b));
}

// ----------------------------------------------------------------------------
// Scratch (device globals; rewritten or zeroed every launch)
// Feature buffers stored fp16 (gather format only; all math fp32)
// ----------------------------------------------------------------------------
__device__ __half g_h1h[NN * HF];   // layer1 transformed features (fp16 mirror)
__device__ float g_as1[NN * NH];
__device__ float g_ad1[NN * NH];
__device__ float g_act[NN * HF];    // layer1 output after ELU (fp32: feeds GEMM2)
__device__ __half g_h2h[NN * NC];   // layer2 transformed features (fp16 mirror)
__device__ float g_as2[NN];
__device__ float g_ad2[NN];
__device__ int   g_deg[NN];
__device__ int   g_cur[NN];
__device__ int   g_off[NN + 1];
__device__ int   g_bsum[128];
__device__ int   g_srcs[NE];        // src ids grouped by dst (CSR), per-segment sorted by src
__device__ int   g_is64;

// ----------------------------------------------------------------------------
// Zero counters + edge dtype detection (jax may emit int32 or int64)
// ----------------------------------------------------------------------------
__global__ void k_zero(const void* src) {
    int i = blockIdx.x * blockDim.x + threadIdx.x;
    if (i < NN) { g_deg[i] = 0; g_cur[i] = 0; }
    if (i == 0) {
        const long long* p = (const long long*)src;
        int ok = 1;
        #pragma unroll
        for (int q = 0; q < 16; q++) {
            long long v = p[q];
            if (v < 0 || v >= NN) ok = 0;
        }
        g_is64 = ok;
    }
}

__device__ __forceinline__ int edge_get(const void* p, int i, int is64) {
    return is64 ? (int)((const long long*)p)[i] : ((const int*)p)[i];
}

// ----------------------------------------------------------------------------
// GEMM1 + fused alpha1: h1 (fp16 out) = x @ W1; as1/ad1 = per-head dots
// 128x128 tile, 256 threads, 8x8 register tile (row-paired f32x2), BK=16,
// double-buffered smem with register prefetch.
// ----------------------------------------------------------------------------
__global__ void k_gemm1(const float* __restrict__ x, const float* __restrict__ W,
                        const float* __restrict__ avs, const float* __restrict__ avd) {
    __shared__ float As[2][16][128];
    __shared__ float Bs[2][16][128];
    int tid = threadIdx.x;
    int tx = tid & 15, ty = tid >> 4;          // 16x16
    int rowBase = blockIdx.x * 128;

    int qa0 = tid,        qa1 = tid + 256;
    int ra0 = qa0 >> 2,   ca0 = (qa0 & 3) * 4;
    int ra1 = qa1 >> 2,   ca1 = (qa1 & 3) * 4;
    int ga0 = rowBase + ra0, ga1 = rowBase + ra1;
    int kb0 = qa0 >> 5,   cb0 = (qa0 & 31) * 4;
    int kb1 = qa1 >> 5,   cb1 = (qa1 & 31) * 4;

    u64 acc2[4][8];
    #pragma unroll
    for (int i = 0; i < 4; i++)
        #pragma unroll
        for (int j = 0; j < 8; j++) acc2[i][j] = 0ULL;

    float4 rA0, rA1, rB0, rB1;

    {
        rA0 = (ga0 < NN) ? *(const float4*)&x[(size_t)ga0 * FIN + 0 + ca0] : make_float4(0,0,0,0);
        rA1 = (ga1 < NN) ? *(const float4*)&x[(size_t)ga1 * FIN + 0 + ca1] : make_float4(0,0,0,0);
        rB0 = *(const float4*)&W[(size_t)(0 + kb0) * HF + cb0];
        rB1 = *(const float4*)&W[(size_t)(0 + kb1) * HF + cb1];
        As[0][ca0 + 0][ra0] = rA0.x; As[0][ca0 + 1][ra0] = rA0.y;
        As[0][ca0 + 2][ra0] = rA0.z; As[0][ca0 + 3][ra0] = rA0.w;
        As[0][ca1 + 0][ra1] = rA1.x; As[0][ca1 + 1][ra1] = rA1.y;
        As[0][ca1 + 2][ra1] = rA1.z; As[0][ca1 + 3][ra1] = rA1.w;
        *((float4*)&Bs[0][kb0][cb0]) = rB0;
        *((float4*)&Bs[0][kb1][cb1]) = rB1;
    }
    __syncthreads();

    #pragma unroll
    for (int t = 0; t < 8; t++) {
        int cur = t & 1;
        if (t < 7) {
            int kt = 16 * (t + 1);
            rA0 = (ga0 < NN) ? *(const float4*)&x[(size_t)ga0 * FIN + kt + ca0] : make_float4(0,0,0,0);
            rA1 = (ga1 < NN) ? *(const float4*)&x[(size_t)ga1 * FIN + kt + ca1] : make_float4(0,0,0,0);
            rB0 = *(const float4*)&W[(size_t)(kt + kb0) * HF + cb0];
            rB1 = *(const float4*)&W[(size_t)(kt + kb1) * HF + cb1];
        }

        #pragma unroll
        for (int k = 0; k < 16; k++) {
            u64 A0 = *(const u64*)&As[cur][k][ty * 8 + 0];
            u64 A1 = *(const u64*)&As[cur][k][ty * 8 + 2];
            u64 A2 = *(const u64*)&As[cur][k][ty * 8 + 4];
            u64 A3 = *(const u64*)&As[cur][k][ty * 8 + 6];
            float4 b0 = *(const float4*)&Bs[cur][k][tx * 8];
            float4 b1 = *(const float4*)&Bs[cur][k][tx * 8 + 4];
            u64 bb[8];
            bb[0] = pack2(b0.x, b0.x); bb[1] = pack2(b0.y, b0.y);
            bb[2] = pack2(b0.z, b0.z); bb[3] = pack2(b0.w, b0.w);
            bb[4] = pack2(b1.x, b1.x); bb[5] = pack2(b1.y, b1.y);
            bb[6] = pack2(b1.z, b1.z); bb[7] = pack2(b1.w, b1.w);
            #pragma unroll
            for (int j = 0; j < 8; j++) {
                fma2(acc2[0][j], A0, bb[j]);
                fma2(acc2[1][j], A1, bb[j]);
                fma2(acc2[2][j], A2, bb[j]);
                fma2(acc2[3][j], A3, bb[j]);
            }
        }

        if (t < 7) {
            int nxt = cur ^ 1;
            __syncthreads();
            As[nxt][ca0 + 0][ra0] = rA0.x; As[nxt][ca0 + 1][ra0] = rA0.y;
            As[nxt][ca0 + 2][ra0] = rA0.z; As[nxt][ca0 + 3][ra0] = rA0.w;
            As[nxt][ca1 + 0][ra1] = rA1.x; As[nxt][ca1 + 1][ra1] = rA1.y;
            As[nxt][ca1 + 2][ra1] = rA1.z; As[nxt][ca1 + 3][ra1] = rA1.w;
            *((float4*)&Bs[nxt][kb0][cb0]) = rB0;
            *((float4*)&Bs[nxt][kb1][cb1]) = rB1;
            __syncthreads();
        }
    }

    float acc[8][8];
    #pragma unroll
    for (int i2 = 0; i2 < 4; i2++)
        #pragma unroll
        for (int j = 0; j < 8; j++) {
            float2 v = unpack2(acc2[i2][j]);
            acc[2 * i2 + 0][j] = v.x;
            acc[2 * i2 + 1][j] = v.y;
        }

    // store h1 as fp16 (thread tx owns cols [tx*8, tx*8+8) -> 16B per row)
    #pragma unroll
    for (int i = 0; i < 8; i++) {
        int grow = rowBase + ty * 8 + i;
        if (grow < NN) {
            __half hb[8];
            #pragma unroll
            for (int j = 0; j < 8; j++) hb[j] = __float2half_rn(acc[i][j]);
            *(uint4*)&g_h1h[(size_t)grow * HF + tx * 8] = *(uint4*)hb;
        }
    }

    // fused alpha epilogue (fp32): thread tx owns cols [tx*8, tx*8+8) -> head tx/2
    float av_s[8], av_d[8];
    #pragma unroll
    for (int j = 0; j < 8; j++) { av_s[j] = avs[tx * 8 + j]; av_d[j] = avd[tx * 8 + j]; }
    #pragma unroll
    for (int i = 0; i < 8; i++) {
        float s = 0.f, d = 0.f;
        #pragma unroll
        for (int j = 0; j < 8; j++) { s += acc[i][j] * av_s[j]; d += acc[i][j] * av_d[j]; }
        s += __shfl_xor_sync(0xffffffffu, s, 1);
        d += __shfl_xor_sync(0xffffffffu, d, 1);
        if ((tx & 1) == 0) {
            int grow = rowBase + ty * 8 + i;
            if (grow < NN) {
                g_as1[grow * NH + (tx >> 1)] = s;
                g_ad1[grow * NH + (tx >> 1)] = d;
            }
        }
    }
}

// ----------------------------------------------------------------------------
// Degree histogram
// ----------------------------------------------------------------------------
__global__ void k_hist(const void* edst) {
    int is64 = g_is64;
    int stride = gridDim.x * blockDim.x;
    for (int e = blockIdx.x * blockDim.x + threadIdx.x; e < NE; e += stride) {
        atomicAdd(&g_deg[edge_get(edst, e, is64)], 1);
    }
}

// ----------------------------------------------------------------------------
// Two-level exclusive scan
// ----------------------------------------------------------------------------
__global__ void k_scan1() {
    __shared__ int sh[1024];
    int tid = threadIdx.x;
    int i = blockIdx.x * 1024 + tid;
    int v = (i < NN) ? g_deg[i] : 0;
    sh[tid] = v;
    __syncthreads();
    #pragma unroll
    for (int ofs = 1; ofs < 1024; ofs <<= 1) {
        int t = (tid >= ofs) ? sh[tid - ofs] : 0;
        __syncthreads();
        sh[tid] += t;
        __syncthreads();
    }
    if (i < NN) g_off[i] = sh[tid] - v;
    if (tid == 1023) g_bsum[blockIdx.x] = sh[1023];
}

__global__ void k_scan2() {
    __shared__ int sh[128];
    int tid = threadIdx.x;
    int v = (tid < NBLK) ? g_bsum[tid] : 0;
    sh[tid] = v;
    __syncthreads();
    #pragma unroll
    for (int ofs = 1; ofs < 128; ofs <<= 1) {
        int t = (tid >= ofs) ? sh[tid - ofs] : 0;
        __syncthreads();
        sh[tid] += t;
        __syncthreads();
    }
    if (tid < NBLK) g_bsum[tid] = sh[tid] - v;   // exclusive
}

__global__ void k_scan3() {
    int i = blockIdx.x * 1024 + threadIdx.x;
    if (i < NN) g_off[i] += g_bsum[blockIdx.x];
    if (i == 0) g_off[NN] = NE;
}

// ----------------------------------------------------------------------------
// Scatter edges into CSR slots
// ----------------------------------------------------------------------------
__global__ void k_scatter(const void* esrc, const void* edst) {
    int is64 = g_is64;
    int stride = gridDim.x * blockDim.x;
    for (int e = blockIdx.x * blockDim.x + threadIdx.x; e < NE; e += stride) {
        int d = edge_get(edst, e, is64);
        int s = edge_get(esrc, e, is64);
        int pos = g_off[d] + atomicAdd(&g_cur[d], 1);
        g_srcs[pos] = s;
    }
}

// ----------------------------------------------------------------------------
// Per-segment sort by src (canonical order => determinism).
// ----------------------------------------------------------------------------
#define SORT_T 128
#define SORT_D 64
__global__ void __launch_bounds__(SORT_T) k_sort() {
    __shared__ int sbuf[SORT_D * SORT_T];
    int t = threadIdx.x;
    int n = blockIdx.x * SORT_T + t;
    if (n >= NN) return;
    int b = g_off[n], e = g_off[n + 1];
    int deg = e - b;
    if (deg <= 1) return;
    if (deg <= SORT_D) {
        for (int i = 0; i < deg; i++) sbuf[i * SORT_T + t] = g_srcs[b + i];
        for (int i = 1; i < deg; i++) {
            int v = sbuf[i * SORT_T + t], j = i - 1;
            while (j >= 0 && sbuf[j * SORT_T + t] > v) {
                sbuf[(j + 1) * SORT_T + t] = sbuf[j * SORT_T + t];
                j--;
            }
            sbuf[(j + 1) * SORT_T + t] = v;
        }
        for (int i = 0; i < deg; i++) g_srcs[b + i] = sbuf[i * SORT_T + t];
    } else {
        for (int i = 1; i < deg; i++) {
            int v = g_srcs[b + i], j = i - 1;
            while (j >= 0 && g_srcs[b + j] > v) { g_srcs[b + j + 1] = g_srcs[b + j]; j--; }
            g_srcs[b + j + 1] = v;
        }
    }
}

// ----------------------------------------------------------------------------
// Layer-1 softmax + aggregate + bias + ELU. Warp per dst node.
// Lane l owns features [l*4, l*4+4) (fp16 gather, fp32 math), head = l/4.
// ----------------------------------------------------------------------------
__global__ void k_agg1(const float* __restrict__ b1) {
    int warp = (blockIdx.x * blockDim.x + threadIdx.x) >> 5;
    int lane = threadIdx.x & 31;
    if (warp >= NN) return;
    int d = warp;
    int beg = g_off[d], end = g_off[d + 1];
    int hd = lane >> 2;
    int f0 = lane * 4;
    float ad = g_ad1[d * NH + hd];

    float sum = 0.f;
    float4 acc = make_float4(0.f, 0.f, 0.f, 0.f);
    if (beg < end) {
        int s = g_srcs[beg];
        float a = g_as1[s * NH + hd];
        uint2 hraw = *(const uint2*)&g_h1h[(size_t)s * HF + f0];
        for (int i = beg + 1; i < end; i++) {
            int s2 = g_srcs[i];
            float a2 = g_as1[s2 * NH + hd];
            uint2 hraw2 = *(const uint2*)&g_h1h[(size_t)s2 * HF + f0];
            float e = a + ad;
            e = fmaxf(e, 0.2f * e);
            float p = __expf(e);
            sum += p;
            float2 f01 = __half22float2(*(__half2*)&hraw.x);
            float2 f23 = __half22float2(*(__half2*)&hraw.y);
            acc.x += p * f01.x; acc.y += p * f01.y; acc.z += p * f23.x; acc.w += p * f23.y;
            a = a2; hraw = hraw2;
        }
        float e = a + ad;
        e = fmaxf(e, 0.2f * e);
        float p = __expf(e);
        sum += p;
        float2 f01 = __half22float2(*(__half2*)&hraw.x);
        float2 f23 = __half22float2(*(__half2*)&hraw.y);
        acc.x += p * f01.x; acc.y += p * f01.y; acc.z += p * f23.x; acc.w += p * f23.y;
    }

    float inv = (end > beg) ? 1.f / sum : 0.f;
    float4 b = *(const float4*)&b1[f0];
    float4 r;
    r.x = acc.x * inv + b.x;
    r.y = acc.y * inv + b.y;
    r.z = acc.z * inv + b.z;
    r.w = acc.w * inv + b.w;
    r.x = r.x > 0.f ? r.x : expm1f(r.x);
    r.y = r.y > 0.f ? r.y : expm1f(r.y);
    r.z = r.z > 0.f ? r.z : expm1f(r.z);
    r.w = r.w > 0.f ? r.w : expm1f(r.w);
    *(float4*)&g_act[(size_t)d * HF + f0] = r;
}

// ----------------------------------------------------------------------------
// GEMM2 + fused alpha2: h2 (fp16 out) = g_act @ W2 (128x40, 4x5/thread, f32x2)
// ----------------------------------------------------------------------------
__global__ void k_gemm2(const float* __restrict__ W,
                        const float* __restrict__ avs, const float* __restrict__ avd) {
    __shared__ float As[16][128];
    __shared__ float Bs[16][NC];
    int tid = threadIdx.x;
    int tx = tid & 7, ty = tid >> 3;
    int rowBase = blockIdx.x * 128;

    u64 acc2[2][5];
    #pragma unroll
    for (int i = 0; i < 2; i++)
        #pragma unroll
        for (int j = 0; j < 5; j++) acc2[i][j] = 0ULL;

    for (int kt = 0; kt < HF; kt += 16) {
        #pragma unroll
        for (int l = 0; l < 2; l++) {
            int q  = tid + l * 256;
            int r  = q >> 2;
            int c4 = q & 3;
            int grow = rowBase + r;
            float4 v = make_float4(0.f, 0.f, 0.f, 0.f);
            if (grow < NN) v = *(const float4*)&g_act[(size_t)grow * HF + kt + c4 * 4];
            As[c4 * 4 + 0][r] = v.x;
            As[c4 * 4 + 1][r] = v.y;
            As[c4 * 4 + 2][r] = v.z;
            As[c4 * 4 + 3][r] = v.w;
        }
        #pragma unroll
        for (int l = 0; l < 3; l++) {
            int idx = tid + l * 256;
            if (idx < 16 * NC) {
                int kr = idx / NC, c = idx % NC;
                Bs[kr][c] = W[(size_t)(kt + kr) * NC + c];
            }
        }
        __syncthreads();

        #pragma unroll
        for (int k = 0; k < 16; k++) {
            u64 A0 = *(const u64*)&As[k][ty * 4 + 0];
            u64 A1 = *(const u64*)&As[k][ty * 4 + 2];
            u64 bb[5];
            #pragma unroll
            for (int j = 0; j < 5; j++) {
                float b = Bs[k][tx * 5 + j];
                bb[j] = pack2(b, b);
            }
            #pragma unroll
            for (int j = 0; j < 5; j++) {
                fma2(acc2[0][j], A0, bb[j]);
                fma2(acc2[1][j], A1, bb[j]);
            }
        }
        __syncthreads();
    }

    float acc[4][5];
    #pragma unroll
    for (int i2 = 0; i2 < 2; i2++)
        #pragma unroll
        for (int j = 0; j < 5; j++) {
            float2 v = unpack2(acc2[i2][j]);
            acc[2 * i2 + 0][j] = v.x;
            acc[2 * i2 + 1][j] = v.y;
        }

    float av_s[5], av_d[5];
    #pragma unroll
    for (int j = 0; j < 5; j++) { av_s[j] = avs[tx * 5 + j]; av_d[j] = avd[tx * 5 + j]; }

    #pragma unroll
    for (int i = 0; i < 4; i++) {
        int grow = rowBase + ty * 4 + i;
        float s = 0.f, d = 0.f;
        #pragma unroll
        for (int j = 0; j < 5; j++) { s += acc[i][j] * av_s[j]; d += acc[i][j] * av_d[j]; }
        #pragma unroll
        for (int o = 1; o < 8; o <<= 1) {
            s += __shfl_xor_sync(0xffffffffu, s, o);
            d += __shfl_xor_sync(0xffffffffu, d, o);
        }
        if (grow < NN) {
            #pragma unroll
            for (int j = 0; j < 5; j++)
                g_h2h[(size_t)grow * NC + tx * 5 + j] = __float2half_rn(acc[i][j]);
            if (tx == 0) { g_as2[grow] = s; g_ad2[grow] = d; }
        }
    }
}

// ----------------------------------------------------------------------------
// Layer-2 softmax + aggregate + bias. Warp per dst node, fp16 gather.
// Lanes 0..19 own 2 output cols each.
// ----------------------------------------------------------------------------
__global__ void k_agg2(const float* __restrict__ b2, float* __restrict__ out) {
    int warp = (blockIdx.x * blockDim.x + threadIdx.x) >> 5;
    int lane = threadIdx.x & 31;
    if (warp >= NN) return;
    int d = warp;
    int beg = g_off[d], end = g_off[d + 1];
    float ad = g_ad2[d];

    float sum = 0.f;
    float2 acc = make_float2(0.f, 0.f);
    int c0 = lane * 2;
    bool act = (lane < 20);
    if (beg < end) {
        int s = g_srcs[beg];
        float a = g_as2[s];
        unsigned hraw = act ? *(const unsigned*)&g_h2h[(size_t)s * NC + c0] : 0u;
        for (int i = beg + 1; i < end; i++) {
            int s2 = g_srcs[i];
            float a2 = g_as2[s2];
            unsigned hraw2 = act ? *(const unsigned*)&g_h2h[(size_t)s2 * NC + c0] : 0u;
            float e = a + ad;
            e = fmaxf(e, 0.2f * e);
            float p = __expf(e);
            sum += p;
            float2 hv = __half22float2(*(__half2*)&hraw);
            acc.x += p * hv.x; acc.y += p * hv.y;
            a = a2; hraw = hraw2;
        }
        float e = a + ad;
        e = fmaxf(e, 0.2f * e);
        float p = __expf(e);
        sum += p;
        float2 hv = __half22float2(*(__half2*)&hraw);
        acc.x += p * hv.x; acc.y += p * hv.y;
    }
    float inv = (end > beg) ? 1.f / sum : 0.f;
    if (act) {
        out[(size_t)d * NC + c0 + 0] = acc.x * inv + b2[c0 + 0];
        out[(size_t)d * NC + c0 + 1] = acc.y * inv + b2[c0 + 1];
    }
}

// ----------------------------------------------------------------------------
// Launch: fork prep chain (s2) parallel with GEMM1 (default), join before agg1
// ----------------------------------------------------------------------------
extern "C" void kernel_launch(void* const* d_in, const int* in_sizes, int n_in,
                              void* d_out, int out_size) {
    static cudaStream_t s2 = 0;
    static cudaEvent_t evFork = 0, evJoin = 0;
    if (!s2) {
        cudaStreamCreateWithFlags(&s2, cudaStreamNonBlocking);
        cudaEventCreateWithFlags(&evFork, cudaEventDisableTiming);
        cudaEventCreateWithFlags(&evJoin, cudaEventDisableTiming);
    }

    const float* x    = (const float*)d_in[0];
    const void*  esrc = d_in[1];
    const void*  edst = d_in[2];
    const float* W1   = (const float*)d_in[3];
    const float* as1  = (const float*)d_in[4];
    const float* ad1  = (const float*)d_in[5];
    const float* b1   = (const float*)d_in[6];
    const float* W2   = (const float*)d_in[7];
    const float* as2  = (const float*)d_in[8];
    const float* ad2  = (const float*)d_in[9];
    const float* b2   = (const float*)d_in[10];
    float* out = (float*)d_out;

    // fork: prep chain on s2
    cudaEventRecord(evFork, 0);
    cudaStreamWaitEvent(s2, evFork, 0);

    k_zero<<<(NN + 255) / 256, 256, 0, s2>>>(esrc);
    k_hist<<<2048, 256, 0, s2>>>(edst);
    k_scan1<<<NBLK, 1024, 0, s2>>>();
    k_scan2<<<1, 128, 0, s2>>>();
    k_scan3<<<NBLK, 1024, 0, s2>>>();
    k_scatter<<<2048, 256, 0, s2>>>(esrc, edst);
    k_sort<<<(NN + SORT_T - 1) / SORT_T, SORT_T, 0, s2>>>();
    cudaEventRecord(evJoin, s2);

    // concurrent: GEMM1 on default stream
    k_gemm1<<<(NN + 127) / 128, 256>>>(x, W1, as1, ad1);

    // join
    cudaStreamWaitEvent(0, evJoin, 0);

    k_agg1<<<(NN * 32 + 255) / 256, 256>>>(b1);
    k_gemm2<<<(NN + 127) / 128, 256>>>(W2, as2, ad2);
    k_agg2<<<(NN * 32 + 255) / 256, 256>>>(b2, out);
}